// round 16
// baseline (speedup 1.0000x reference)
#include <cuda_runtime.h>
#include <cstddef>

// HBV fused time-scan — 2 CELLS PER THREAD (intra-thread ILP).
// Two independent recurrences per thread interleave in one instruction
// stream, filling the 56-cyc soil-chain stalls without barriers/SMEM
// (cross-warp splits R12-R14 all paid more in coordination than they won).
// Adjacent cells -> LDG.64 inputs and STG.64 outputs (halves load/store issue).
// 79 blocks x 64 thr = 158 warps on SMSP0/1 of 79 SMs, uniform.

#define NSTEP  730
#define NGRID  10000
#define PFD    5
#define NCHUNK (NSTEP / PFD)      // 146 (even)
#define NEARZERO 1e-5f

__device__ __forceinline__ float fast_exp2(float v) {
    float r;
    asm("ex2.approx.ftz.f32 %0, %1;" : "=f"(r) : "f"(v));
    return r;   // MUFU.EX2
}

__global__ __launch_bounds__(64, 1)
void hbv_kernel(const float* __restrict__ x,
                const float* __restrict__ params,
                float* __restrict__ out)
{
    const int t  = blockIdx.x * 64 + threadIdx.x;   // pair index
    int c0 = 2 * t;
    const bool valid = (c0 < NGRID);                // NGRID even -> pair all-or-none
    if (!valid) c0 = NGRID - 2;

    // ---- per-cell parameters (last timestep only) ----
    float BETA[2], FC[2], K1[2], K2[2], PERCmax[2], UZL[2], TT[2],
          CFMAX[2], CFR[2], CWH[2], invLPFC[2], blgi[2], K1m[2], K01[2];
#pragma unroll
    for (int k = 0; k < 2; ++k) {
        const float* p = params + ((size_t)(NSTEP - 1) * NGRID + (size_t)(c0 + k)) * 12;
        BETA[k]    = 1.0f   + p[0]  * 5.0f;
        FC[k]      = 50.0f  + p[1]  * 950.0f;
        const float K0 = 0.05f + p[2] * 0.85f;
        K1[k]      = 0.01f  + p[3]  * 0.49f;
        K2[k]      = 0.001f + p[4]  * 0.199f;
        const float LP = 0.2f + p[5] * 0.8f;
        PERCmax[k] =          p[6]  * 10.0f;
        UZL[k]     =          p[7]  * 100.0f;
        TT[k]      = -2.5f  + p[8]  * 5.0f;
        CFMAX[k]   = 0.5f   + p[9]  * 9.5f;
        CFR[k]     =          p[10] * 0.1f;
        CWH[k]     =          p[11] * 0.2f;
        invLPFC[k] = 1.0f / (LP * FC[k]);
        blgi[k]    = BETA[k] * __log2f(1.0f / FC[k]);   // (SM/FC)^B = exp2(B*lgSM + blgi)
        K1m[k]     = 1.0f - K1[k];
        K01[k]     = K0 * K1m[k];                        // Q0+Q1 = K01*u + K1*s1
    }

    float SP[2], MW[2], SM[2], SUZ[2], SLZ[2];
#pragma unroll
    for (int k = 0; k < 2; ++k) { SP[k] = MW[k] = SM[k] = SUZ[k] = SLZ[k] = 0.001f; }

    const size_t n = (size_t)NSTEP * NGRID;
    float* qp = out + c0;              // Qsim
    float* ap = out + n + c0;          // AET
    float* sp = out + 2 * n + c0;      // SWE
    const float* xb = x + (size_t)c0 * 3;   // 8B-aligned (c0 even)

    // ping-pong input buffers: 6 floats/step as 3x float2
    float2 A[PFD][3], B[PFD][3];

#define LOADC(BUF, R0)                                                       \
    {                                                                        \
        _Pragma("unroll")                                                    \
        for (int j = 0; j < PFD; ++j) {                                      \
            const float2* v = (const float2*)(xb + (size_t)((R0) + j) * (NGRID * 3)); \
            BUF[j][0] = v[0]; BUF[j][1] = v[1]; BUF[j][2] = v[2];            \
        }                                                                    \
    }

#define STEPS(BUF)                                                           \
    {                                                                        \
        _Pragma("unroll")                                                    \
        for (int j = 0; j < PFD; ++j) {                                      \
            float P[2], T[2], E[2];                                          \
            P[0] = BUF[j][0].x; T[0] = BUF[j][0].y; E[0] = BUF[j][1].x;      \
            P[1] = BUF[j][1].y; T[1] = BUF[j][2].x; E[1] = BUF[j][2].y;      \
            float lg[2], rt[2], sw[2], SMn[2], ET[2], Qs[2];                 \
            _Pragma("unroll")                                                \
            for (int k = 0; k < 2; ++k) lg[k] = __log2f(SM[k]);              \
            _Pragma("unroll")                                                \
            for (int k = 0; k < 2; ++k) {          /* snow ladder */         \
                const float RAIN = (T[k] >= TT[k]) ? P[k] : 0.0f;            \
                const float m    = CFMAX[k] * (T[k] - TT[k]);                \
                const float sel  = (m >= 0.0f) ? m : (CFR[k] * m);           \
                const float S1   = SP[k] + (P[k] - RAIN);                    \
                const float nn   = fminf(fmaxf(sel, -MW[k]), S1);            \
                SP[k] = S1 - nn;                                             \
                MW[k] = MW[k] + nn;                                          \
                const float ts = fmaxf(fmaf(-CWH[k], SP[k], MW[k]), 0.0f);   \
                MW[k] -= ts;                                                 \
                rt[k] = RAIN + ts;                                           \
            }                                                                \
            _Pragma("unroll")                                                \
            for (int k = 0; k < 2; ++k)                                      \
                sw[k] = fast_exp2(fmaf(BETA[k], lg[k], blgi[k]));            \
            _Pragma("unroll")                                                \
            for (int k = 0; k < 2; ++k) {          /* soil + routing */      \
                const float a   = SM[k] + rt[k];                             \
                SMn[k] = fmaxf(fmaf(-rt[k], sw[k], a), SM[k]); /* min(sw,1) folded */ \
                const float c1  = E[k] * invLPFC[k];                         \
                ET[k] = fminf(fminf(SMn[k] * c1, E[k]), SMn[k]);             \
                SM[k] = fmaxf(fmaxf(fmaf(-c1, SMn[k], SMn[k]), SMn[k] - E[k]), NEARZERO); \
                const float rex  = (a - SMn[k]) + fmaxf(SMn[k] - FC[k], 0.0f); \
                const float SUZa = SUZ[k] + rex;                             \
                const float PERC = fminf(SUZa, PERCmax[k]);                  \
                const float s1   = SUZa - PERC;                              \
                const float u    = fmaxf(s1 - UZL[k], 0.0f);                 \
                const float t1   = K01[k] * u;                               \
                const float Q01  = fmaf(K1[k], s1, t1);                      \
                SUZ[k] = fmaf(K1m[k], s1, -t1);                              \
                SLZ[k] += PERC;                                              \
                const float Q2 = K2[k] * SLZ[k];                             \
                SLZ[k] -= Q2;                                                \
                Qs[k] = Q01 + Q2;                                            \
            }                                                                \
            if (valid) {                                                     \
                *(float2*)qp = make_float2(Qs[0], Qs[1]);                    \
                *(float2*)ap = make_float2(ET[0], ET[1]);                    \
                *(float2*)sp = make_float2(SP[0], SP[1]);                    \
            }                                                                \
            qp += NGRID; ap += NGRID; sp += NGRID;                           \
        }                                                                    \
    }

    // ---- pipeline: ping-pong, prefetch one chunk ahead ----
    LOADC(A, 0);
    for (int c = 0; c < NCHUNK; c += 2) {
        { const int r1 = (c + 1 < NCHUNK) ? (c + 1) * PFD : c * PFD;       LOADC(B, r1); }
        STEPS(A);
        { const int r2 = (c + 2 < NCHUNK) ? (c + 2) * PFD : (c + 1) * PFD; LOADC(A, r2); }
        STEPS(B);
    }
}

extern "C" void kernel_launch(void* const* d_in, const int* in_sizes, int n_in,
                              void* d_out, int out_size)
{
    const float* x      = (const float*)d_in[0];
    const float* params = (const float*)d_in[1];
    float* out          = (float*)d_out;

    // 5000 cell-pairs -> 79 blocks x 64 threads (5056 pairs, tail clamped)
    hbv_kernel<<<79, 64>>>(x, params, out);
}